// round 3
// baseline (speedup 1.0000x reference)
#include <cuda_runtime.h>
#include <cstdint>

// Problem constants (fixed shapes per reference)
#define NSPANS 4096
#define TMAX   16
#define HDIM   768
#define H4     192          // HDIM / 4 (float4 lanes per row)
#define REPR4  576          // 3 * H4 float4 per span repr
#define NPAIRS 16384
#define SL     2048         // S * L

#define NREPR_BLOCKS    256
#define SPANS_PER_BLOCK 16  // NSPANS / NREPR_BLOCKS

// Scratch: span representations [NSPANS, 3*HDIM] = 37.75 MB
__device__ float4 g_reprs[NSPANS * REPR4];
// Per-span ready flags (reset every launch by zero_flags)
__device__ int g_flags[NSPANS];

__global__ void zero_flags()
{
    g_flags[blockIdx.x * 1024 + threadIdx.x] = 0;
}

// Fused kernel.
//  bids [0, 256):      repr producers — 16 spans each, 2 spans per iteration
//                      (threads 0-191 = span A, 192-383 = span B). Never wait.
//  bids [256, 16640):  pair consumers — spin on the two span flags, then
//                      stream the 4608-float row out with evict-first stores.
// Deadlock-free: all 256 producer blocks fit in scheduling wave 1 (min
// resident capacity >= 444 blocks at 384 thr / 24ish regs), and producers
// have no dependencies.
__global__ __launch_bounds__(384) void fused_kernel(
    const float* __restrict__ hidden,
    const int*   __restrict__ span_doc,
    const int*   __restrict__ span_tok,
    const int*   __restrict__ span_len,
    const int*   __restrict__ pair_i,
    const int*   __restrict__ pair_j,
    float4*      __restrict__ out)
{
    const int bid = blockIdx.x;
    const int tid = threadIdx.x;

    if (bid < NREPR_BLOCKS) {
        // ---------------- producer path ----------------
        const int half = tid / H4;        // 0 or 1
        const int lane = tid - half * H4; // 0..191
        const int base = bid * SPANS_PER_BLOCK;

        #pragma unroll 1
        for (int it = 0; it < SPANS_PER_BLOCK / 2; ++it) {
            const int n = base + it * 2 + half;

            const int doc = __ldg(span_doc + n);
            const int len = __ldg(span_len + n);     // 1..16

            const float4* __restrict__ src =
                reinterpret_cast<const float4*>(hidden) + (size_t)doc * SL * H4;
            const int* __restrict__ toks = span_tok + n * TMAX;

            float4 first = make_float4(0.f, 0.f, 0.f, 0.f);
            float4 last  = first;
            float4 acc   = first;

            for (int t = 0; t < len; ++t) {
                const int tok = __ldg(toks + t);
                const float4 v = __ldg(src + (size_t)tok * H4 + lane);
                acc.x += v.x; acc.y += v.y; acc.z += v.z; acc.w += v.w;
                if (t == 0) first = v;
                last = v;
            }

            const float inv = 1.0f / (float)len;
            const float4 mean = make_float4(acc.x * inv, acc.y * inv,
                                            acc.z * inv, acc.w * inv);

            float4* __restrict__ dst = g_reprs + (size_t)n * REPR4;
            dst[lane]          = first;
            dst[H4 + lane]     = mean;
            dst[2 * H4 + lane] = last;

            // Release: make this span's repr visible, then publish flag.
            __threadfence();
            __syncthreads();
            if (lane == 0) atomicExch(&g_flags[n], 1);
        }
        return;
    }

    // ---------------- consumer path ----------------
    const int p = bid - NREPR_BLOCKS;
    __shared__ int s_pi, s_pj;

    if (tid == 0) {
        const int pi = __ldg(pair_i + p);
        const int pj = __ldg(pair_j + p);
        while (atomicAdd(&g_flags[pi], 0) == 0) __nanosleep(200);
        while (atomicAdd(&g_flags[pj], 0) == 0) __nanosleep(200);
        __threadfence();   // acquire: order repr reads after flag observation
        s_pi = pi;
        s_pj = pj;
    }
    __syncthreads();

    const int pi = s_pi;
    const int pj = s_pj;

    const float4* __restrict__ ri = g_reprs + (size_t)pi * REPR4;
    const float4* __restrict__ rj = g_reprs + (size_t)pj * REPR4;
    float4* __restrict__ o = out + (size_t)p * (2 * REPR4);

    const float4 v0 = __ldg(ri + tid);
    const float4 v1 = (tid < 192) ? __ldg(ri + (tid + 384))
                                  : __ldg(rj + (tid - 192));
    const float4 v2 = __ldg(rj + (tid + 192));

    __stcs(o + tid,       v0);
    __stcs(o + tid + 384, v1);
    __stcs(o + tid + 768, v2);
}

extern "C" void kernel_launch(void* const* d_in, const int* in_sizes, int n_in,
                              void* d_out, int out_size)
{
    const float* hidden   = (const float*)d_in[0];
    const int*   span_doc = (const int*)  d_in[1];
    const int*   span_tok = (const int*)  d_in[2];
    const int*   span_len = (const int*)  d_in[3];
    const int*   pair_i   = (const int*)  d_in[4];
    const int*   pair_j   = (const int*)  d_in[5];
    float4*      out      = (float4*)     d_out;

    zero_flags<<<NSPANS / 1024, 1024>>>();
    fused_kernel<<<NREPR_BLOCKS + NPAIRS, 384>>>(
        hidden, span_doc, span_tok, span_len, pair_i, pair_j, out);
}

// round 5
// speedup vs baseline: 1.6796x; 1.6796x over previous
#include <cuda_runtime.h>
#include <cstdint>

// Problem constants (fixed shapes per reference)
#define NSPANS 4096
#define TMAX   16
#define HDIM   768
#define H4     192          // HDIM / 4 (float4 lanes per row)
#define NPAIRS 16384
#define SL     2048         // S * L

// Scratch: only the mean vectors [NSPANS, HDIM] = 12.6 MB.
// first/last are verbatim hidden rows -> re-gathered from L2 in kernel 2.
__device__ float4 g_mean[NSPANS * H4];
// Per-span {first_row_off, last_row_off} in float4 units into hidden.
__device__ int2 g_info[NSPANS];

// Kernel 1: one block per span, 192 threads = one float4 lane each.
// Computes the masked mean; records first/last row offsets.
__global__ __launch_bounds__(H4) void reprs_kernel(
    const float* __restrict__ hidden,
    const int*   __restrict__ span_doc,
    const int*   __restrict__ span_tok,
    const int*   __restrict__ span_len)
{
    const int n    = blockIdx.x;
    const int lane = threadIdx.x;            // 0..191

    const int doc = __ldg(span_doc + n);
    const int len = __ldg(span_len + n);     // 1..16

    const float4* __restrict__ base =
        reinterpret_cast<const float4*>(hidden) + (size_t)doc * SL * H4;
    const int* __restrict__ toks = span_tok + n * TMAX;

    float4 acc = make_float4(0.f, 0.f, 0.f, 0.f);
    int tok0 = 0, tokL = 0;

    for (int t = 0; t < len; ++t) {
        const int tok = __ldg(toks + t);
        const float4 v = __ldg(base + (size_t)tok * H4 + lane);
        acc.x += v.x; acc.y += v.y; acc.z += v.z; acc.w += v.w;
        if (t == 0) tok0 = tok;
        tokL = tok;
    }

    const float inv = 1.0f / (float)len;
    g_mean[n * H4 + lane] = make_float4(acc.x * inv, acc.y * inv,
                                        acc.z * inv, acc.w * inv);

    if (lane == 0) {
        const int docbase = doc * SL;
        g_info[n] = make_int2((docbase + tok0) * H4, (docbase + tokL) * H4);
    }
}

// Kernel 2: one block per pair, 384 threads. Output row layout (float4 units):
//   [ first_i(192) mean_i(192) last_i(192) first_j(192) mean_j(192) last_j(192) ]
// Thread tid covers lanes {tid, tid+384, tid+768}:
//   tid       : tid<192 -> first_i          else mean_i
//   tid+384   : tid<192 -> last_i           else first_j
//   tid+768   : tid<192 -> mean_j           else last_j
// first/last come straight from L2-resident hidden; mean from g_mean.
// All three loads issued before the evict-first stores.
__global__ __launch_bounds__(384) void pairs_kernel(
    const float* __restrict__ hidden,
    const int*   __restrict__ pair_i,
    const int*   __restrict__ pair_j,
    float4*      __restrict__ out)
{
    const int p   = blockIdx.x;
    const int tid = threadIdx.x;
    const int pi  = __ldg(pair_i + p);
    const int pj  = __ldg(pair_j + p);

    const int2 ii = __ldg(&g_info[pi]);
    const int2 ij = __ldg(&g_info[pj]);

    const float4* __restrict__ hid4 = reinterpret_cast<const float4*>(hidden);
    float4* __restrict__ o = out + (size_t)p * 1152;

    const bool lo = (tid < 192);
    const int  t2 = tid - 192;

    const float4 v0 = lo ? __ldg(hid4 + ii.x + tid)
                         : __ldg(g_mean + pi * H4 + t2);
    const float4 v1 = lo ? __ldg(hid4 + ii.y + tid)
                         : __ldg(hid4 + ij.x + t2);
    const float4 v2 = lo ? __ldg(g_mean + pj * H4 + tid)
                         : __ldg(hid4 + ij.y + t2);

    __stcs(o + tid,       v0);
    __stcs(o + tid + 384, v1);
    __stcs(o + tid + 768, v2);
}

extern "C" void kernel_launch(void* const* d_in, const int* in_sizes, int n_in,
                              void* d_out, int out_size)
{
    const float* hidden   = (const float*)d_in[0];
    const int*   span_doc = (const int*)  d_in[1];
    const int*   span_tok = (const int*)  d_in[2];
    const int*   span_len = (const int*)  d_in[3];
    const int*   pair_i   = (const int*)  d_in[4];
    const int*   pair_j   = (const int*)  d_in[5];
    float4*      out      = (float4*)     d_out;

    reprs_kernel<<<NSPANS, H4>>>(hidden, span_doc, span_tok, span_len);
    pairs_kernel<<<NPAIRS, 384>>>(hidden, pair_i, pair_j, out);
}